// round 3
// baseline (speedup 1.0000x reference)
#include <cuda_runtime.h>
#include <math.h>

#define DIM 128
#define NMAX 50000
#define CHUNK 128
#define NCMAX 512

// ---------------- scratch (allocation-free) ----------------
static constexpr size_t SZ_ND   = (size_t)NMAX * DIM;          // 6,400,000
static constexpr size_t OFF_SUMS = 0;
static constexpr size_t OFF_CNT  = OFF_SUMS + SZ_ND;
static constexpr size_t OFF_X0   = OFF_CNT + 50048;
static constexpr size_t OFF_X1   = OFF_X0 + SZ_ND;
static constexpr size_t OFF_A    = OFF_X1 + SZ_ND;
static constexpr size_t OFF_B    = OFF_A + SZ_ND;
static constexpr size_t OFF_P    = OFF_B + SZ_ND;
static constexpr size_t OFF_Q    = OFF_P + (size_t)NCMAX * DIM;
static constexpr size_t OFF_C    = OFF_Q + (size_t)NCMAX * DIM;
static constexpr size_t SCRATCH_TOTAL = OFF_C + (size_t)NCMAX * DIM;

__device__ __align__(16) float g_scratch[SCRATCH_TOTAL];

// ---------------- kernels ----------------

__global__ void k_zero(float* __restrict__ sums, float* __restrict__ cnt, int N) {
    size_t i = (size_t)blockIdx.x * blockDim.x + threadIdx.x;
    size_t stride = (size_t)gridDim.x * blockDim.x;
    size_t n4 = (size_t)N * DIM / 4;
    float4 z = make_float4(0.f, 0.f, 0.f, 0.f);
    for (size_t k = i; k < n4; k += stride) ((float4*)sums)[k] = z;
    for (size_t k = i; k < (size_t)N; k += stride) cnt[k] = 0.f;
}

// warp-per-edge gather + vector atomic scatter
__global__ void k_scatter(const int* __restrict__ ei, const int* __restrict__ et,
                          const int* __restrict__ tt, const float* __restrict__ ew,
                          const float* __restrict__ ent, const float* __restrict__ rel,
                          const float* __restrict__ tim,
                          float* __restrict__ sums, float* __restrict__ cnt, int E) {
    int e = (int)(((size_t)blockIdx.x * blockDim.x + threadIdx.x) >> 5);
    if (e >= E) return;
    int lane = threadIdx.x & 31;
    int src = ei[e], dst = ei[E + e];
    int r = et[e], ti = tt[e];
    float w = ew[e];
    float4 a = ((const float4*)(ent + (size_t)src * DIM))[lane];
    float4 b = ((const float4*)(rel + (size_t)r * DIM))[lane];
    float4 c = ((const float4*)(tim + (size_t)ti * DIM))[lane];
    float4 m;
    m.x = (a.x + b.x + c.x) * w;
    m.y = (a.y + b.y + c.y) * w;
    m.z = (a.z + b.z + c.z) * w;
    m.w = (a.w + b.w + c.w) * w;
    atomicAdd(((float4*)(sums + (size_t)dst * DIM)) + lane, m);
    if (lane == 0) atomicAdd(cnt + dst, w);
}

// warp-per-row: mean, L2-normalize, permute-gather
__global__ void k_normperm(const int* __restrict__ perm, const float* __restrict__ sums,
                           const float* __restrict__ cnt, float* __restrict__ xo, int N) {
    int row = (int)(((size_t)blockIdx.x * blockDim.x + threadIdx.x) >> 5);
    if (row >= N) return;
    int lane = threadIdx.x & 31;
    int p = perm[row];
    float inv = 1.f / fmaxf(cnt[p], 1.f);
    float4 v = ((const float4*)(sums + (size_t)p * DIM))[lane];
    v.x *= inv; v.y *= inv; v.z *= inv; v.w *= inv;
    float sq = v.x * v.x + v.y * v.y + v.z * v.z + v.w * v.w;
#pragma unroll
    for (int o = 16; o > 0; o >>= 1) sq += __shfl_xor_sync(0xffffffffu, sq, o);
    float s = 1.f / fmaxf(sqrtf(sq), 1e-12f);
    v.x *= s; v.y *= s; v.z *= s; v.w *= s;
    ((float4*)(xo + (size_t)row * DIM))[lane] = v;
}

__device__ __forceinline__ float sigmoidf_fast(float v) {
    return 1.f / (1.f + __expf(-v));
}

// zg = x @ Wi + bi ; a = sigmoid(g)*A[d] ; b = B[d]*z
// 256 threads: jg = t&31 (4 z-cols + 4 g-cols), rg = t>>5 (4 rows) -> 32 rows/tile
__global__ void __launch_bounds__(256, 1) k_inproj(
    const float* __restrict__ x, const float* __restrict__ Wi, const float* __restrict__ bi,
    const float* __restrict__ Av, const float* __restrict__ Bv,
    float* __restrict__ aout, float* __restrict__ bout, int N) {
    extern __shared__ float sm[];
    float* w_sm = sm;                   // 32768 floats
    float* bi_sm = sm + 32768;          // 256
    float* A_sm = bi_sm + 256;          // 128
    float* B_sm = A_sm + 128;           // 128
    float* x_sm = B_sm + 128;           // 32*128 = 4096
    int t = threadIdx.x;
    for (int k = t; k < 8192; k += 256) ((float4*)w_sm)[k] = ((const float4*)Wi)[k];
    if (t < 64) ((float4*)bi_sm)[t] = ((const float4*)bi)[t];
    if (t < 32) ((float4*)A_sm)[t] = ((const float4*)Av)[t];
    else if (t < 64) ((float4*)B_sm)[t - 32] = ((const float4*)Bv)[t - 32];
    __syncthreads();
    int jg = t & 31, rg = t >> 5;
    int ntiles = (N + 31) >> 5;
    for (int tile = blockIdx.x; tile < ntiles; tile += gridDim.x) {
        int row0 = tile << 5;
        __syncthreads();
        for (int k = t; k < 1024; k += 256) {
            int row = row0 + (k >> 5);
            float4 v = make_float4(0.f, 0.f, 0.f, 0.f);
            if (row < N) v = ((const float4*)x)[(size_t)row0 * 32 + k];
            ((float4*)x_sm)[k] = v;
        }
        __syncthreads();
        float az[4][4], ag[4][4];
#pragma unroll
        for (int r = 0; r < 4; r++)
#pragma unroll
            for (int q = 0; q < 4; q++) { az[r][q] = 0.f; ag[r][q] = 0.f; }
        const float* xr = x_sm + (rg * 4) * DIM;
#pragma unroll 4
        for (int d = 0; d < DIM; d++) {
            float4 wz = ((const float4*)(w_sm + d * 256))[jg];
            float4 wg = ((const float4*)(w_sm + d * 256 + 128))[jg];
#pragma unroll
            for (int r = 0; r < 4; r++) {
                float xv = xr[r * DIM + d];
                az[r][0] = fmaf(wz.x, xv, az[r][0]);
                az[r][1] = fmaf(wz.y, xv, az[r][1]);
                az[r][2] = fmaf(wz.z, xv, az[r][2]);
                az[r][3] = fmaf(wz.w, xv, az[r][3]);
                ag[r][0] = fmaf(wg.x, xv, ag[r][0]);
                ag[r][1] = fmaf(wg.y, xv, ag[r][1]);
                ag[r][2] = fmaf(wg.z, xv, ag[r][2]);
                ag[r][3] = fmaf(wg.w, xv, ag[r][3]);
            }
        }
        float4 bz = ((const float4*)bi_sm)[jg];
        float4 bg = ((const float4*)bi_sm)[jg + 32];
        float4 B4 = ((const float4*)B_sm)[jg];
        float4 A4 = ((const float4*)A_sm)[jg];
#pragma unroll
        for (int r = 0; r < 4; r++) {
            int row = row0 + rg * 4 + r;
            if (row < N) {
                float4 ob, oa;
                ob.x = B4.x * (az[r][0] + bz.x);
                ob.y = B4.y * (az[r][1] + bz.y);
                ob.z = B4.z * (az[r][2] + bz.z);
                ob.w = B4.w * (az[r][3] + bz.w);
                oa.x = A4.x * sigmoidf_fast(ag[r][0] + bg.x);
                oa.y = A4.y * sigmoidf_fast(ag[r][1] + bg.y);
                oa.z = A4.z * sigmoidf_fast(ag[r][2] + bg.z);
                oa.w = A4.w * sigmoidf_fast(ag[r][3] + bg.w);
                ((float4*)(bout + (size_t)row * DIM))[jg] = ob;
                ((float4*)(aout + (size_t)row * DIM))[jg] = oa;
            }
        }
    }
}

// pass 1: per-chunk (P = prod a, Q = scan-from-zero)
__global__ void k_scan1(const float* __restrict__ a, const float* __restrict__ b,
                        float* __restrict__ P, float* __restrict__ Q, int N) {
    int c = blockIdx.x, d = threadIdx.x;
    int i0 = c * CHUNK, i1 = min(N, i0 + CHUNK);
    float p = 1.f, q = 0.f;
#pragma unroll 4
    for (int i = i0; i < i1; i++) {
        float av = a[(size_t)i * DIM + d];
        float bv = b[(size_t)i * DIM + d];
        q = fmaf(av, q, bv);
        p *= av;
    }
    P[c * DIM + d] = p;
    Q[c * DIM + d] = q;
}

// compose chunk carries (single block, smem-staged so the serial chain stays on LDS latency)
__global__ void k_carry(const float* __restrict__ P, const float* __restrict__ Q,
                        float* __restrict__ C, int NC) {
    extern __shared__ float sm[];
    float* Ps = sm;
    float* Qs = sm + 64 * DIM;
    int d = threadIdx.x;
    float h = 0.f;
    for (int base = 0; base < NC; base += 64) {
        int cnt = min(64, NC - base);
        __syncthreads();
        for (int k = d; k < cnt * DIM; k += DIM) {
            Ps[k] = P[base * DIM + k];
            Qs[k] = Q[base * DIM + k];
        }
        __syncthreads();
        for (int k = 0; k < cnt; k++) {
            C[(size_t)(base + k) * DIM + d] = h;
            h = fmaf(Ps[k * DIM + d], h, Qs[k * DIM + d]);
        }
    }
}

// pass 2: replay chunk with incoming carry, emit h
__global__ void k_scan2(const float* __restrict__ a, const float* __restrict__ b,
                        const float* __restrict__ C, float* __restrict__ h, int N) {
    int c = blockIdx.x, d = threadIdx.x;
    float hv = C[(size_t)c * DIM + d];
    int i0 = c * CHUNK, i1 = min(N, i0 + CHUNK);
#pragma unroll 4
    for (int i = i0; i < i1; i++) {
        hv = fmaf(a[(size_t)i * DIM + d], hv, b[(size_t)i * DIM + d]);
        h[(size_t)i * DIM + d] = hv;
    }
}

// y = x + h@Wo + bo ; LayerNorm -> xo
// 256 threads: jg = t&31 (4 cols), rg = t>>5 (8 rows) -> 64 rows/tile
__global__ void __launch_bounds__(256, 2) k_outproj(
    const float* __restrict__ x, const float* __restrict__ h,
    const float* __restrict__ Wo, const float* __restrict__ bo,
    const float* __restrict__ lng, const float* __restrict__ lnb,
    float* __restrict__ xo, int N) {
    extern __shared__ float sm[];
    float* w_sm = sm;               // 16384 floats
    float* bo_sm = sm + 16384;      // 128
    float* g_sm = bo_sm + 128;      // 128
    float* be_sm = g_sm + 128;      // 128
    float* h_sm = be_sm + 128;      // 64*128 = 8192
    int t = threadIdx.x;
    for (int k = t; k < 4096; k += 256) ((float4*)w_sm)[k] = ((const float4*)Wo)[k];
    if (t < 32) ((float4*)bo_sm)[t] = ((const float4*)bo)[t];
    else if (t < 64) ((float4*)g_sm)[t - 32] = ((const float4*)lng)[t - 32];
    else if (t < 96) ((float4*)be_sm)[t - 64] = ((const float4*)lnb)[t - 64];
    __syncthreads();
    int jg = t & 31, rg = t >> 5;
    int ntiles = (N + 63) >> 6;
    for (int tile = blockIdx.x; tile < ntiles; tile += gridDim.x) {
        int row0 = tile << 6;
        __syncthreads();
        for (int k = t; k < 2048; k += 256) {
            int row = row0 + (k >> 5);
            float4 v = make_float4(0.f, 0.f, 0.f, 0.f);
            if (row < N) v = ((const float4*)h)[(size_t)row0 * 32 + k];
            ((float4*)h_sm)[k] = v;
        }
        __syncthreads();
        float acc[8][4];
#pragma unroll
        for (int r = 0; r < 8; r++)
#pragma unroll
            for (int q = 0; q < 4; q++) acc[r][q] = 0.f;
        const float* hr = h_sm + (rg * 8) * DIM;
#pragma unroll 4
        for (int d = 0; d < DIM; d++) {
            float4 wv = ((const float4*)(w_sm + d * DIM))[jg];
#pragma unroll
            for (int r = 0; r < 8; r++) {
                float hv = hr[r * DIM + d];
                acc[r][0] = fmaf(wv.x, hv, acc[r][0]);
                acc[r][1] = fmaf(wv.y, hv, acc[r][1]);
                acc[r][2] = fmaf(wv.z, hv, acc[r][2]);
                acc[r][3] = fmaf(wv.w, hv, acc[r][3]);
            }
        }
        float4 b4 = ((const float4*)bo_sm)[jg];
        float4 g4 = ((const float4*)g_sm)[jg];
        float4 e4 = ((const float4*)be_sm)[jg];
#pragma unroll
        for (int r = 0; r < 8; r++) {
            int row = row0 + rg * 8 + r;
            if (row < N) {   // uniform across the warp (row depends only on rg, r)
                float4 xv = ((const float4*)x)[(size_t)row * 32 + jg];
                float4 y;
                y.x = acc[r][0] + b4.x + xv.x;
                y.y = acc[r][1] + b4.y + xv.y;
                y.z = acc[r][2] + b4.z + xv.z;
                y.w = acc[r][3] + b4.w + xv.w;
                float s = y.x + y.y + y.z + y.w;
                float sq = y.x * y.x + y.y * y.y + y.z * y.z + y.w * y.w;
#pragma unroll
                for (int o = 16; o > 0; o >>= 1) {
                    s += __shfl_xor_sync(0xffffffffu, s, o);
                    sq += __shfl_xor_sync(0xffffffffu, sq, o);
                }
                float mu = s * (1.f / 128.f);
                float var = sq * (1.f / 128.f) - mu * mu;
                float rs = rsqrtf(var + 1e-5f);
                float4 o4;
                o4.x = (y.x - mu) * rs * g4.x + e4.x;
                o4.y = (y.y - mu) * rs * g4.y + e4.y;
                o4.z = (y.z - mu) * rs * g4.z + e4.z;
                o4.w = (y.w - mu) * rs * g4.w + e4.w;
                ((float4*)(xo + (size_t)row * DIM))[jg] = o4;
            }
        }
    }
}

// ---------------- launch ----------------
static constexpr int SMEM_IN = (32768 + 256 + 128 + 128 + 32 * 128) * 4;   // 149504 B
static constexpr int SMEM_OUT = (16384 + 128 + 128 + 128 + 64 * 128) * 4;  // 99840 B

extern "C" void kernel_launch(void* const* d_in, const int* in_sizes, int n_in,
                              void* d_out, int out_size) {
    const int* edge_index = (const int*)d_in[0];
    const int* edge_type = (const int*)d_in[1];
    const int* edge_time = (const int*)d_in[2];
    const float* edge_weight = (const float*)d_in[3];
    const int* perm = (const int*)d_in[4];
    const float* ent = (const float*)d_in[5];
    const float* rel = (const float*)d_in[6];
    const float* tim = (const float*)d_in[7];
    const float* Wi = (const float*)d_in[8];
    const float* bi = (const float*)d_in[9];
    const float* Wo = (const float*)d_in[10];
    const float* bo = (const float*)d_in[11];
    const float* Av = (const float*)d_in[12];
    const float* Bv = (const float*)d_in[13];
    const float* lng = (const float*)d_in[14];
    const float* lnb = (const float*)d_in[15];
    float* out = (float*)d_out;

    int E = in_sizes[1];
    int N = in_sizes[4];
    int L = in_sizes[12] / DIM;

    float* base = nullptr;
    cudaGetSymbolAddress((void**)&base, g_scratch);
    float* sums = base + OFF_SUMS;
    float* cnt = base + OFF_CNT;
    float* x0 = base + OFF_X0;
    float* x1 = base + OFF_X1;
    float* ab_a = base + OFF_A;
    float* ab_b = base + OFF_B;
    float* Pb = base + OFF_P;
    float* Qb = base + OFF_Q;
    float* Cb = base + OFF_C;

    cudaFuncSetAttribute(k_inproj, cudaFuncAttributeMaxDynamicSharedMemorySize, SMEM_IN);
    cudaFuncSetAttribute(k_outproj, cudaFuncAttributeMaxDynamicSharedMemorySize, SMEM_OUT);
    cudaFuncSetAttribute(k_carry, cudaFuncAttributeMaxDynamicSharedMemorySize, 65536);

    k_zero<<<2048, 256>>>(sums, cnt, N);

    int sblocks = (int)(((size_t)E * 32 + 255) / 256);
    k_scatter<<<sblocks, 256>>>(edge_index, edge_type, edge_time, edge_weight,
                                ent, rel, tim, sums, cnt, E);

    k_normperm<<<(N + 7) / 8, 256>>>(perm, sums, cnt, x0, N);

    int NC = (N + CHUNK - 1) / CHUNK;
    float* ping[2] = {x0, x1};
    const float* xin = x0;
    for (int l = 0; l < L; l++) {
        k_inproj<<<148, 256, SMEM_IN>>>(xin, Wi + (size_t)l * DIM * 2 * DIM,
                                        bi + (size_t)l * 2 * DIM,
                                        Av + (size_t)l * DIM, Bv + (size_t)l * DIM,
                                        ab_a, ab_b, N);
        k_scan1<<<NC, DIM>>>(ab_a, ab_b, Pb, Qb, N);
        k_carry<<<1, DIM, 65536>>>(Pb, Qb, Cb, NC);
        k_scan2<<<NC, DIM>>>(ab_a, ab_b, Cb, sums, N);   // reuse sums as h buffer
        float* xout = (l == L - 1) ? out : ping[(l + 1) & 1];
        k_outproj<<<296, 256, SMEM_OUT>>>(xin, sums, Wo + (size_t)l * DIM * DIM,
                                          bo + (size_t)l * DIM,
                                          lng + (size_t)l * DIM, lnb + (size_t)l * DIM,
                                          xout, N);
        xin = xout;
    }
}

// round 5
// speedup vs baseline: 1.0361x; 1.0361x over previous
#include <cuda_runtime.h>
#include <math.h>

#define DIM 128
#define NMAX 50000
#define CHUNK 128
#define NCMAX 512

// ---------------- scratch (allocation-free) ----------------
static constexpr size_t SZ_ND   = (size_t)NMAX * DIM;          // 6,400,000
static constexpr size_t OFF_SUMS = 0;
static constexpr size_t OFF_CNT  = OFF_SUMS + SZ_ND;
static constexpr size_t OFF_X0   = OFF_CNT + 50048;
static constexpr size_t OFF_X1   = OFF_X0 + SZ_ND;
static constexpr size_t OFF_A    = OFF_X1 + SZ_ND;
static constexpr size_t OFF_B    = OFF_A + SZ_ND;
static constexpr size_t OFF_P    = OFF_B + SZ_ND;
static constexpr size_t OFF_Q    = OFF_P + (size_t)NCMAX * DIM;
static constexpr size_t OFF_C    = OFF_Q + (size_t)NCMAX * DIM;
static constexpr size_t SCRATCH_TOTAL = OFF_C + (size_t)NCMAX * DIM;

__device__ __align__(16) float g_scratch[SCRATCH_TOTAL];

// ---------------- f32x2 packed helpers (sm_10x) ----------------
typedef unsigned long long u64;

__device__ __forceinline__ u64 dup2(float v) {
    u64 r;
    asm("mov.b64 %0, {%1, %1};" : "=l"(r) : "f"(v));
    return r;
}
__device__ __forceinline__ void fma2(u64& d, u64 a, u64 b) {
    asm("fma.rn.f32x2 %0, %1, %2, %0;" : "+l"(d) : "l"(a), "l"(b));
}
__device__ __forceinline__ float2 unpack2(u64 v) {
    float2 f;
    asm("mov.b64 {%0, %1}, %2;" : "=f"(f.x), "=f"(f.y) : "l"(v));
    return f;
}

// ---------------- kernels ----------------

__global__ void k_zero(float* __restrict__ sums, float* __restrict__ cnt, int N) {
    size_t i = (size_t)blockIdx.x * blockDim.x + threadIdx.x;
    size_t stride = (size_t)gridDim.x * blockDim.x;
    size_t n4 = (size_t)N * DIM / 4;
    float4 z = make_float4(0.f, 0.f, 0.f, 0.f);
    for (size_t k = i; k < n4; k += stride) ((float4*)sums)[k] = z;
    for (size_t k = i; k < (size_t)N; k += stride) cnt[k] = 0.f;
}

// warp-per-edge gather + vector atomic scatter
__global__ void k_scatter(const int* __restrict__ ei, const int* __restrict__ et,
                          const int* __restrict__ tt, const float* __restrict__ ew,
                          const float* __restrict__ ent, const float* __restrict__ rel,
                          const float* __restrict__ tim,
                          float* __restrict__ sums, float* __restrict__ cnt, int E) {
    int e = (int)(((size_t)blockIdx.x * blockDim.x + threadIdx.x) >> 5);
    if (e >= E) return;
    int lane = threadIdx.x & 31;
    int src = ei[e], dst = ei[E + e];
    int r = et[e], ti = tt[e];
    float w = ew[e];
    float4 a = ((const float4*)(ent + (size_t)src * DIM))[lane];
    float4 b = ((const float4*)(rel + (size_t)r * DIM))[lane];
    float4 c = ((const float4*)(tim + (size_t)ti * DIM))[lane];
    float4 m;
    m.x = (a.x + b.x + c.x) * w;
    m.y = (a.y + b.y + c.y) * w;
    m.z = (a.z + b.z + c.z) * w;
    m.w = (a.w + b.w + c.w) * w;
    atomicAdd(((float4*)(sums + (size_t)dst * DIM)) + lane, m);
    if (lane == 0) atomicAdd(cnt + dst, w);
}

// warp-per-row: mean, L2-normalize, permute-gather
__global__ void k_normperm(const int* __restrict__ perm, const float* __restrict__ sums,
                           const float* __restrict__ cnt, float* __restrict__ xo, int N) {
    int row = (int)(((size_t)blockIdx.x * blockDim.x + threadIdx.x) >> 5);
    if (row >= N) return;
    int lane = threadIdx.x & 31;
    int p = perm[row];
    float inv = 1.f / fmaxf(cnt[p], 1.f);
    float4 v = ((const float4*)(sums + (size_t)p * DIM))[lane];
    v.x *= inv; v.y *= inv; v.z *= inv; v.w *= inv;
    float sq = v.x * v.x + v.y * v.y + v.z * v.z + v.w * v.w;
#pragma unroll
    for (int o = 16; o > 0; o >>= 1) sq += __shfl_xor_sync(0xffffffffu, sq, o);
    float s = 1.f / fmaxf(sqrtf(sq), 1e-12f);
    v.x *= s; v.y *= s; v.z *= s; v.w *= s;
    ((float4*)(xo + (size_t)row * DIM))[lane] = v;
}

__device__ __forceinline__ float sigmoidf_fast(float v) {
    return 1.f / (1.f + __expf(-v));
}

// zg = x @ Wi + bi ; a = sigmoid(g)*A[d] ; b = B[d]*z
// 256 threads: jg = t&31 (4 z-cols + 4 g-cols), rg = t>>5, 8 rows/thread -> 64 rows/tile
// FFMA packed as f32x2: 32 FFMA2/thread per d-step.
__global__ void __launch_bounds__(256, 1) k_inproj(
    const float* __restrict__ x, const float* __restrict__ Wi, const float* __restrict__ bi,
    const float* __restrict__ Av, const float* __restrict__ Bv,
    float* __restrict__ aout, float* __restrict__ bout, int N) {
    extern __shared__ float sm[];
    float* w_sm = sm;                   // 32768 floats (128KB)
    float* bi_sm = sm + 32768;          // 256
    float* A_sm = bi_sm + 256;          // 128
    float* B_sm = A_sm + 128;           // 128
    float* x_sm = B_sm + 128;           // 64*128 = 8192 (32KB)
    int t = threadIdx.x;
    for (int k = t; k < 8192; k += 256) ((float4*)w_sm)[k] = ((const float4*)Wi)[k];
    if (t < 64) ((float4*)bi_sm)[t] = ((const float4*)bi)[t];
    if (t < 32) ((float4*)A_sm)[t] = ((const float4*)Av)[t];
    else if (t < 64) ((float4*)B_sm)[t - 32] = ((const float4*)Bv)[t - 32];
    __syncthreads();
    int jg = t & 31, rg = t >> 5;
    int ntiles = (N + 63) >> 6;
    for (int tile = blockIdx.x; tile < ntiles; tile += gridDim.x) {
        int row0 = tile << 6;
        __syncthreads();
        for (int k = t; k < 2048; k += 256) {
            int row = row0 + (k >> 5);
            float4 v = make_float4(0.f, 0.f, 0.f, 0.f);
            if (row < N) v = ((const float4*)x)[(size_t)row0 * 32 + k];
            ((float4*)x_sm)[k] = v;
        }
        __syncthreads();
        u64 az[8][2], ag[8][2];
#pragma unroll
        for (int r = 0; r < 8; r++) {
            az[r][0] = 0ull; az[r][1] = 0ull;
            ag[r][0] = 0ull; ag[r][1] = 0ull;
        }
        const float* xr = x_sm + (rg * 8) * DIM;
#pragma unroll 2
        for (int d = 0; d < DIM; d++) {
            ulonglong2 wz = ((const ulonglong2*)(w_sm + d * 256))[jg];
            ulonglong2 wg = ((const ulonglong2*)(w_sm + d * 256 + 128))[jg];
#pragma unroll
            for (int r = 0; r < 8; r++) {
                u64 xx = dup2(xr[r * DIM + d]);
                fma2(az[r][0], wz.x, xx);
                fma2(az[r][1], wz.y, xx);
                fma2(ag[r][0], wg.x, xx);
                fma2(ag[r][1], wg.y, xx);
            }
        }
        float4 bz = ((const float4*)bi_sm)[jg];
        float4 bg = ((const float4*)bi_sm)[jg + 32];
        float4 B4 = ((const float4*)B_sm)[jg];
        float4 A4 = ((const float4*)A_sm)[jg];
#pragma unroll
        for (int r = 0; r < 8; r++) {
            int row = row0 + rg * 8 + r;
            if (row < N) {
                float2 z0 = unpack2(az[r][0]);
                float2 z1 = unpack2(az[r][1]);
                float2 g0 = unpack2(ag[r][0]);
                float2 g1 = unpack2(ag[r][1]);
                float4 ob, oa;
                ob.x = B4.x * (z0.x + bz.x);
                ob.y = B4.y * (z0.y + bz.y);
                ob.z = B4.z * (z1.x + bz.z);
                ob.w = B4.w * (z1.y + bz.w);
                oa.x = A4.x * sigmoidf_fast(g0.x + bg.x);
                oa.y = A4.y * sigmoidf_fast(g0.y + bg.y);
                oa.z = A4.z * sigmoidf_fast(g1.x + bg.z);
                oa.w = A4.w * sigmoidf_fast(g1.y + bg.w);
                ((float4*)(bout + (size_t)row * DIM))[jg] = ob;
                ((float4*)(aout + (size_t)row * DIM))[jg] = oa;
            }
        }
    }
}

// pass 1: per-chunk (P = prod a, Q = scan-from-zero)
__global__ void k_scan1(const float* __restrict__ a, const float* __restrict__ b,
                        float* __restrict__ P, float* __restrict__ Q, int N) {
    int c = blockIdx.x, d = threadIdx.x;
    int i0 = c * CHUNK, i1 = min(N, i0 + CHUNK);
    float p = 1.f, q = 0.f;
#pragma unroll 4
    for (int i = i0; i < i1; i++) {
        float av = a[(size_t)i * DIM + d];
        float bv = b[(size_t)i * DIM + d];
        q = fmaf(av, q, bv);
        p *= av;
    }
    P[c * DIM + d] = p;
    Q[c * DIM + d] = q;
}

// compose chunk carries (single block, smem-staged so the serial chain stays on LDS latency)
__global__ void k_carry(const float* __restrict__ P, const float* __restrict__ Q,
                        float* __restrict__ C, int NC) {
    extern __shared__ float sm[];
    float* Ps = sm;
    float* Qs = sm + 64 * DIM;
    int d = threadIdx.x;
    float h = 0.f;
    for (int base = 0; base < NC; base += 64) {
        int cnt = min(64, NC - base);
        __syncthreads();
        for (int k = d; k < cnt * DIM; k += DIM) {
            Ps[k] = P[base * DIM + k];
            Qs[k] = Q[base * DIM + k];
        }
        __syncthreads();
        for (int k = 0; k < cnt; k++) {
            C[(size_t)(base + k) * DIM + d] = h;
            h = fmaf(Ps[k * DIM + d], h, Qs[k * DIM + d]);
        }
    }
}

// pass 2: replay chunk with incoming carry, emit h
__global__ void k_scan2(const float* __restrict__ a, const float* __restrict__ b,
                        const float* __restrict__ C, float* __restrict__ h, int N) {
    int c = blockIdx.x, d = threadIdx.x;
    float hv = C[(size_t)c * DIM + d];
    int i0 = c * CHUNK, i1 = min(N, i0 + CHUNK);
#pragma unroll 4
    for (int i = i0; i < i1; i++) {
        hv = fmaf(a[(size_t)i * DIM + d], hv, b[(size_t)i * DIM + d]);
        h[(size_t)i * DIM + d] = hv;
    }
}

// y = x + h@Wo + bo ; LayerNorm -> xo
// 256 threads: jg = t&31 (4 cols), rg = t>>5 (8 rows each) -> 64 rows/tile, f32x2 packed
__global__ void __launch_bounds__(256, 2) k_outproj(
    const float* __restrict__ x, const float* __restrict__ h,
    const float* __restrict__ Wo, const float* __restrict__ bo,
    const float* __restrict__ lng, const float* __restrict__ lnb,
    float* __restrict__ xo, int N) {
    extern __shared__ float sm[];
    float* w_sm = sm;               // 16384 floats
    float* bo_sm = sm + 16384;      // 128
    float* g_sm = bo_sm + 128;      // 128
    float* be_sm = g_sm + 128;      // 128
    float* h_sm = be_sm + 128;      // 64*128 = 8192
    int t = threadIdx.x;
    for (int k = t; k < 4096; k += 256) ((float4*)w_sm)[k] = ((const float4*)Wo)[k];
    if (t < 32) ((float4*)bo_sm)[t] = ((const float4*)bo)[t];
    else if (t < 64) ((float4*)g_sm)[t - 32] = ((const float4*)lng)[t - 32];
    else if (t < 96) ((float4*)be_sm)[t - 64] = ((const float4*)lnb)[t - 64];
    __syncthreads();
    int jg = t & 31, rg = t >> 5;
    int ntiles = (N + 63) >> 6;
    for (int tile = blockIdx.x; tile < ntiles; tile += gridDim.x) {
        int row0 = tile << 6;
        __syncthreads();
        for (int k = t; k < 2048; k += 256) {
            int row = row0 + (k >> 5);
            float4 v = make_float4(0.f, 0.f, 0.f, 0.f);
            if (row < N) v = ((const float4*)h)[(size_t)row0 * 32 + k];
            ((float4*)h_sm)[k] = v;
        }
        __syncthreads();
        u64 acc[8][2];
#pragma unroll
        for (int r = 0; r < 8; r++) { acc[r][0] = 0ull; acc[r][1] = 0ull; }
        const float* hr = h_sm + (rg * 8) * DIM;
#pragma unroll 2
        for (int d = 0; d < DIM; d++) {
            ulonglong2 wv = ((const ulonglong2*)(w_sm + d * DIM))[jg];
#pragma unroll
            for (int r = 0; r < 8; r++) {
                u64 hh = dup2(hr[r * DIM + d]);
                fma2(acc[r][0], wv.x, hh);
                fma2(acc[r][1], wv.y, hh);
            }
        }
        float4 b4 = ((const float4*)bo_sm)[jg];
        float4 g4 = ((const float4*)g_sm)[jg];
        float4 e4 = ((const float4*)be_sm)[jg];
#pragma unroll
        for (int r = 0; r < 8; r++) {
            int row = row0 + rg * 8 + r;
            if (row < N) {   // uniform across the warp (row depends only on rg, r)
                float2 a0 = unpack2(acc[r][0]);
                float2 a1 = unpack2(acc[r][1]);
                float4 xv = ((const float4*)x)[(size_t)row * 32 + jg];
                float4 y;
                y.x = a0.x + b4.x + xv.x;
                y.y = a0.y + b4.y + xv.y;
                y.z = a1.x + b4.z + xv.z;
                y.w = a1.y + b4.w + xv.w;
                float s = y.x + y.y + y.z + y.w;
                float sq = y.x * y.x + y.y * y.y + y.z * y.z + y.w * y.w;
#pragma unroll
                for (int o = 16; o > 0; o >>= 1) {
                    s += __shfl_xor_sync(0xffffffffu, s, o);
                    sq += __shfl_xor_sync(0xffffffffu, sq, o);
                }
                float mu = s * (1.f / 128.f);
                float var = sq * (1.f / 128.f) - mu * mu;
                float rs = rsqrtf(var + 1e-5f);
                float4 o4;
                o4.x = (y.x - mu) * rs * g4.x + e4.x;
                o4.y = (y.y - mu) * rs * g4.y + e4.y;
                o4.z = (y.z - mu) * rs * g4.z + e4.z;
                o4.w = (y.w - mu) * rs * g4.w + e4.w;
                ((float4*)(xo + (size_t)row * DIM))[jg] = o4;
            }
        }
    }
}

// ---------------- launch ----------------
static constexpr int SMEM_IN = (32768 + 256 + 128 + 128 + 64 * 128) * 4;   // 165,888 B
static constexpr int SMEM_OUT = (16384 + 128 + 128 + 128 + 64 * 128) * 4;  // 99,840 B

extern "C" void kernel_launch(void* const* d_in, const int* in_sizes, int n_in,
                              void* d_out, int out_size) {
    const int* edge_index = (const int*)d_in[0];
    const int* edge_type = (const int*)d_in[1];
    const int* edge_time = (const int*)d_in[2];
    const float* edge_weight = (const float*)d_in[3];
    const int* perm = (const int*)d_in[4];
    const float* ent = (const float*)d_in[5];
    const float* rel = (const float*)d_in[6];
    const float* tim = (const float*)d_in[7];
    const float* Wi = (const float*)d_in[8];
    const float* bi = (const float*)d_in[9];
    const float* Wo = (const float*)d_in[10];
    const float* bo = (const float*)d_in[11];
    const float* Av = (const float*)d_in[12];
    const float* Bv = (const float*)d_in[13];
    const float* lng = (const float*)d_in[14];
    const float* lnb = (const float*)d_in[15];
    float* out = (float*)d_out;

    int E = in_sizes[1];
    int N = in_sizes[4];
    int L = in_sizes[12] / DIM;

    float* base = nullptr;
    cudaGetSymbolAddress((void**)&base, g_scratch);
    float* sums = base + OFF_SUMS;
    float* cnt = base + OFF_CNT;
    float* x0 = base + OFF_X0;
    float* x1 = base + OFF_X1;
    float* ab_a = base + OFF_A;
    float* ab_b = base + OFF_B;
    float* Pb = base + OFF_P;
    float* Qb = base + OFF_Q;
    float* Cb = base + OFF_C;

    cudaFuncSetAttribute(k_inproj, cudaFuncAttributeMaxDynamicSharedMemorySize, SMEM_IN);
    cudaFuncSetAttribute(k_outproj, cudaFuncAttributeMaxDynamicSharedMemorySize, SMEM_OUT);
    cudaFuncSetAttribute(k_carry, cudaFuncAttributeMaxDynamicSharedMemorySize, 65536);

    k_zero<<<2048, 256>>>(sums, cnt, N);

    int sblocks = (int)(((size_t)E * 32 + 255) / 256);
    k_scatter<<<sblocks, 256>>>(edge_index, edge_type, edge_time, edge_weight,
                                ent, rel, tim, sums, cnt, E);

    k_normperm<<<(N + 7) / 8, 256>>>(perm, sums, cnt, x0, N);

    int NC = (N + CHUNK - 1) / CHUNK;
    float* ping[2] = {x0, x1};
    const float* xin = x0;
    for (int l = 0; l < L; l++) {
        k_inproj<<<148, 256, SMEM_IN>>>(xin, Wi + (size_t)l * DIM * 2 * DIM,
                                        bi + (size_t)l * 2 * DIM,
                                        Av + (size_t)l * DIM, Bv + (size_t)l * DIM,
                                        ab_a, ab_b, N);
        k_scan1<<<NC, DIM>>>(ab_a, ab_b, Pb, Qb, N);
        k_carry<<<1, DIM, 65536>>>(Pb, Qb, Cb, NC);
        k_scan2<<<NC, DIM>>>(ab_a, ab_b, Cb, sums, N);   // reuse sums as h buffer
        float* xout = (l == L - 1) ? out : ping[(l + 1) & 1];
        k_outproj<<<296, 256, SMEM_OUT>>>(xin, sums, Wo + (size_t)l * DIM * DIM,
                                          bo + (size_t)l * DIM,
                                          lng + (size_t)l * DIM, lnb + (size_t)l * DIM,
                                          xout, N);
        xin = xout;
    }
}